// round 16
// baseline (speedup 1.0000x reference)
#include <cuda_runtime.h>
#include <cstdint>

// Problem constants
#define B_TOT   65536
#define KDIM    128     // z feature dim (reduction dim of GEMM)
#define NOUT    1024    // K*RANK
#define QROWS   64
#define QCOLS   16

// 256 MB scratch for w = z @ W^T + b + 1e-6  (device global: allocation-free)
__device__ float g_w[(size_t)B_TOT * NOUT];

// ---------------------------------------------------------------------------
// GEMM: g_w[B,1024] = z[B,128] @ W^T + bias + 1e-6
// 128x128 block tile, 8x8 micro-tile per thread, packed f32x2 FMA (FFMA2).
// ---------------------------------------------------------------------------
#define BM 128
#define BN 128
#define BK 16
#define SPAD 132   // smem row stride (floats); keeps 16B alignment of rows

__global__ void __launch_bounds__(256, 2)
gemm_kernel(const float* __restrict__ z,
            const float* __restrict__ W,
            const float* __restrict__ bias)
{
    __shared__ __align__(16) float As[BK][SPAD];   // z^T tile: As[k][m]
    __shared__ __align__(16) float Bs[BK][SPAD];   // W^T tile: Bs[k][n]

    const int tid = threadIdx.x;
    const int bm0 = blockIdx.y * BM;
    const int bn0 = blockIdx.x * BN;
    const int tm  = tid >> 4;      // 0..15  (M groups of 8)
    const int tn  = tid & 15;      // 0..15  (N groups of 8)

    // packed accumulators: acc[i][jj] = {col 2jj, col 2jj+1} for row i
    unsigned long long acc[8][4];
#pragma unroll
    for (int i = 0; i < 8; i++)
#pragma unroll
        for (int jj = 0; jj < 4; jj++) acc[i][jj] = 0ull;

    const int lrow = tid >> 2;          // 0..63
    const int lcol = (tid & 3) << 2;    // 0,4,8,12

    const float* zA = z + (size_t)(bm0 + lrow)      * KDIM + lcol;
    const float* zB = z + (size_t)(bm0 + lrow + 64) * KDIM + lcol;
    const float* wA = W + (size_t)(bn0 + lrow)      * KDIM + lcol;
    const float* wB = W + (size_t)(bn0 + lrow + 64) * KDIM + lcol;

    for (int k0 = 0; k0 < KDIM; k0 += BK) {
        float4 a0 = *(const float4*)(zA + k0);
        float4 a1 = *(const float4*)(zB + k0);
        float4 b0 = *(const float4*)(wA + k0);
        float4 b1 = *(const float4*)(wB + k0);
        __syncthreads();
        As[lcol+0][lrow]    = a0.x; As[lcol+1][lrow]    = a0.y;
        As[lcol+2][lrow]    = a0.z; As[lcol+3][lrow]    = a0.w;
        As[lcol+0][lrow+64] = a1.x; As[lcol+1][lrow+64] = a1.y;
        As[lcol+2][lrow+64] = a1.z; As[lcol+3][lrow+64] = a1.w;
        Bs[lcol+0][lrow]    = b0.x; Bs[lcol+1][lrow]    = b0.y;
        Bs[lcol+2][lrow]    = b0.z; Bs[lcol+3][lrow]    = b0.w;
        Bs[lcol+0][lrow+64] = b1.x; Bs[lcol+1][lrow+64] = b1.y;
        Bs[lcol+2][lrow+64] = b1.z; Bs[lcol+3][lrow+64] = b1.w;
        __syncthreads();

#pragma unroll
        for (int kk = 0; kk < BK; kk++) {
            float av[8];
            *(float4*)(av)     = *(const float4*)&As[kk][tm*8];
            *(float4*)(av + 4) = *(const float4*)&As[kk][tm*8 + 4];
            unsigned long long bv[4];
            const unsigned long long* bp =
                (const unsigned long long*)&Bs[kk][tn*8];
            bv[0] = bp[0]; bv[1] = bp[1]; bv[2] = bp[2]; bv[3] = bp[3];
#pragma unroll
            for (int i = 0; i < 8; i++) {
                unsigned long long ad;
                asm("mov.b64 %0, {%1, %1};"
                    : "=l"(ad) : "r"(__float_as_uint(av[i])));
#pragma unroll
                for (int jj = 0; jj < 4; jj++) {
                    asm("fma.rn.f32x2 %0, %1, %2, %0;"
                        : "+l"(acc[i][jj]) : "l"(ad), "l"(bv[jj]));
                }
            }
        }
    }

    // epilogue: + bias + 1e-6, write scratch
    float bb[8];
    *(float4*)(bb)     = *(const float4*)(bias + bn0 + tn*8);
    *(float4*)(bb + 4) = *(const float4*)(bias + bn0 + tn*8 + 4);
#pragma unroll
    for (int i = 0; i < 8; i++) {
        float res[8];
#pragma unroll
        for (int jj = 0; jj < 4; jj++) {
            unsigned lo, hi;
            asm("mov.b64 {%0, %1}, %2;" : "=r"(lo), "=r"(hi) : "l"(acc[i][jj]));
            res[2*jj]   = __uint_as_float(lo) + bb[2*jj]   + 1e-6f;
            res[2*jj+1] = __uint_as_float(hi) + bb[2*jj+1] + 1e-6f;
        }
        float* o = g_w + (size_t)(bm0 + tm*8 + i) * NOUT + bn0 + tn*8;
        *(float4*)o       = make_float4(res[0], res[1], res[2], res[3]);
        *(float4*)(o + 4) = make_float4(res[4], res[5], res[6], res[7]);
    }
}

// ---------------------------------------------------------------------------
// Householder QR (LAPACK convention) — one warp per 64x16 matrix.
// Lane l owns rows l and l+32. A in smem (pad 17 -> conflict-free columns),
// Q accumulated in registers. All dots of a step are batched for SHFL ILP.
// ---------------------------------------------------------------------------
__device__ __forceinline__ float warpsum(float v) {
    v += __shfl_xor_sync(0xffffffffu, v, 16);
    v += __shfl_xor_sync(0xffffffffu, v, 8);
    v += __shfl_xor_sync(0xffffffffu, v, 4);
    v += __shfl_xor_sync(0xffffffffu, v, 2);
    v += __shfl_xor_sync(0xffffffffu, v, 1);
    return v;
}

#define QR_WARPS 4

__global__ void __launch_bounds__(32 * QR_WARPS)
qr_kernel(float* __restrict__ out)
{
    __shared__ float Am[QR_WARPS][QROWS][QCOLS + 1];
    __shared__ float Taus[QR_WARPS][QCOLS];

    const int warp = threadIdx.x >> 5;
    const int lane = threadIdx.x & 31;
    const size_t b = (size_t)blockIdx.x * QR_WARPS + warp;

    float (*a)[QCOLS + 1] = Am[warp];
    float* taus = Taus[warp];

    // load matrix: rows lane and lane+32
    const float* src = g_w + b * NOUT;
#pragma unroll
    for (int c0 = 0; c0 < QCOLS; c0 += 4) {
        float4 v = *(const float4*)(src + lane * QCOLS + c0);
        a[lane][c0]   = v.x; a[lane][c0+1] = v.y;
        a[lane][c0+2] = v.z; a[lane][c0+3] = v.w;
        float4 u = *(const float4*)(src + (lane + 32) * QCOLS + c0);
        a[lane+32][c0]   = u.x; a[lane+32][c0+1] = u.y;
        a[lane+32][c0+2] = u.z; a[lane+32][c0+3] = u.w;
    }
    __syncwarp();

    // ---- factorization: 16 Householder reflectors ----
    for (int j = 0; j < QCOLS; j++) {
        float x0  = a[j][j];
        float c0v = (lane >= j) ? a[lane][j] : 0.f;
        float c1v = a[lane + 32][j];
        float p = warpsum(c0v * c0v + c1v * c1v);   // ||x||^2 incl. x0

        float beta = -copysignf(sqrtf(p), x0);      // LAPACK slarfg
        float tau  = (beta - x0) / beta;
        float sc   = 1.0f / (x0 - beta);

        float v0 = (lane == j) ? 1.0f : c0v * sc;   // lane<j: c0v=0 -> v0=0
        float v1 = c1v * sc;

        if (lane >= j) a[lane][j] = v0;             // store v (diag gets 1)
        a[lane + 32][j] = v1;
        if (lane == 0) taus[j] = tau;

        // trailing update: batch the independent dots for SHFL ILP
        float pd[QCOLS];
#pragma unroll
        for (int r = 0; r < QCOLS; r++)
            if (r > j) pd[r] = v0 * a[lane][r] + v1 * a[lane + 32][r];
#pragma unroll
        for (int r = 0; r < QCOLS; r++)
            if (r > j) pd[r] = warpsum(pd[r]);
#pragma unroll
        for (int r = 0; r < QCOLS; r++)
            if (r > j) {
                float td = tau * pd[r];
                a[lane][r]      -= td * v0;
                a[lane + 32][r] -= td * v1;
            }
        __syncwarp();
    }

    // ---- Q = H_0 ... H_15 * I(64x16), backward accumulation (org2r) ----
    float q0[QCOLS], q1[QCOLS];
#pragma unroll
    for (int c = 0; c < QCOLS; c++) {
        q0[c] = (lane == c) ? 1.0f : 0.0f;
        q1[c] = 0.0f;
    }
    for (int j = QCOLS - 1; j >= 0; j--) {
        float tau = taus[j];
        float v0  = (lane >= j) ? a[lane][j] : 0.f;  // v[j]=1 stored
        float v1  = a[lane + 32][j];
        float pd[QCOLS];
#pragma unroll
        for (int r = 0; r < QCOLS; r++)
            if (r >= j) pd[r] = v0 * q0[r] + v1 * q1[r];
#pragma unroll
        for (int r = 0; r < QCOLS; r++)
            if (r >= j) pd[r] = warpsum(pd[r]);
#pragma unroll
        for (int r = 0; r < QCOLS; r++)
            if (r >= j) {
                float td = tau * pd[r];
                q0[r] -= td * v0;
                q1[r] -= td * v1;
            }
    }

    // write Q
    float* dst = out + b * NOUT + lane * QCOLS;
#pragma unroll
    for (int c0 = 0; c0 < QCOLS; c0 += 4) {
        *(float4*)(dst + c0)       = make_float4(q0[c0], q0[c0+1], q0[c0+2], q0[c0+3]);
        *(float4*)(dst + 512 + c0) = make_float4(q1[c0], q1[c0+1], q1[c0+2], q1[c0+3]);
    }
}

// ---------------------------------------------------------------------------
extern "C" void kernel_launch(void* const* d_in, const int* in_sizes, int n_in,
                              void* d_out, int out_size)
{
    const float* z    = (const float*)d_in[0];   // [65536,128]
    const float* W    = (const float*)d_in[1];   // [1024,128]
    const float* bias = (const float*)d_in[2];   // [1024]
    float* out = (float*)d_out;                  // [65536,64,16] fp32

    dim3 ggrid(NOUT / BN, B_TOT / BM);           // (8, 512)
    gemm_kernel<<<ggrid, 256>>>(z, W, bias);
    qr_kernel<<<B_TOT / QR_WARPS, 32 * QR_WARPS>>>(out);
}

// round 17
// speedup vs baseline: 1.5301x; 1.5301x over previous
#include <cuda_runtime.h>
#include <cstdint>

// Problem constants
#define B_TOT   65536
#define KDIM    128     // z feature dim (reduction dim of GEMM)
#define NOUT    1024    // K*RANK
#define QROWS   64
#define QCOLS   16

// 256 MB scratch for w = z @ W^T + b + 1e-6  (device global: allocation-free)
__device__ float g_w[(size_t)B_TOT * NOUT];

// ---------------------------------------------------------------------------
// GEMM: g_w[B,1024] = z[B,128] @ W^T + bias + 1e-6
// 128x128 block tile, 8x8 micro-tile per thread, packed f32x2 FMA (FFMA2).
// ---------------------------------------------------------------------------
#define BM 128
#define BN 128
#define BK 16
#define SPAD 132   // smem row stride (floats); keeps 16B alignment of rows

__global__ void __launch_bounds__(256, 2)
gemm_kernel(const float* __restrict__ z,
            const float* __restrict__ W,
            const float* __restrict__ bias)
{
    __shared__ __align__(16) float As[BK][SPAD];   // z^T tile: As[k][m]
    __shared__ __align__(16) float Bs[BK][SPAD];   // W^T tile: Bs[k][n]

    const int tid = threadIdx.x;
    const int bm0 = blockIdx.y * BM;
    const int bn0 = blockIdx.x * BN;
    const int tm  = tid >> 4;      // 0..15  (M groups of 8)
    const int tn  = tid & 15;      // 0..15  (N groups of 8)

    // packed accumulators: acc[i][jj] = {col 2jj, col 2jj+1} for row i
    unsigned long long acc[8][4];
#pragma unroll
    for (int i = 0; i < 8; i++)
#pragma unroll
        for (int jj = 0; jj < 4; jj++) acc[i][jj] = 0ull;

    const int lrow = tid >> 2;          // 0..63
    const int lcol = (tid & 3) << 2;    // 0,4,8,12

    const float* zA = z + (size_t)(bm0 + lrow)      * KDIM + lcol;
    const float* zB = z + (size_t)(bm0 + lrow + 64) * KDIM + lcol;
    const float* wA = W + (size_t)(bn0 + lrow)      * KDIM + lcol;
    const float* wB = W + (size_t)(bn0 + lrow + 64) * KDIM + lcol;

    for (int k0 = 0; k0 < KDIM; k0 += BK) {
        float4 a0 = *(const float4*)(zA + k0);
        float4 a1 = *(const float4*)(zB + k0);
        float4 b0 = *(const float4*)(wA + k0);
        float4 b1 = *(const float4*)(wB + k0);
        __syncthreads();
        As[lcol+0][lrow]    = a0.x; As[lcol+1][lrow]    = a0.y;
        As[lcol+2][lrow]    = a0.z; As[lcol+3][lrow]    = a0.w;
        As[lcol+0][lrow+64] = a1.x; As[lcol+1][lrow+64] = a1.y;
        As[lcol+2][lrow+64] = a1.z; As[lcol+3][lrow+64] = a1.w;
        Bs[lcol+0][lrow]    = b0.x; Bs[lcol+1][lrow]    = b0.y;
        Bs[lcol+2][lrow]    = b0.z; Bs[lcol+3][lrow]    = b0.w;
        Bs[lcol+0][lrow+64] = b1.x; Bs[lcol+1][lrow+64] = b1.y;
        Bs[lcol+2][lrow+64] = b1.z; Bs[lcol+3][lrow+64] = b1.w;
        __syncthreads();

#pragma unroll
        for (int kk = 0; kk < BK; kk++) {
            float av[8];
            *(float4*)(av)     = *(const float4*)&As[kk][tm*8];
            *(float4*)(av + 4) = *(const float4*)&As[kk][tm*8 + 4];
            unsigned long long bv[4];
            const unsigned long long* bp =
                (const unsigned long long*)&Bs[kk][tn*8];
            bv[0] = bp[0]; bv[1] = bp[1]; bv[2] = bp[2]; bv[3] = bp[3];
#pragma unroll
            for (int i = 0; i < 8; i++) {
                unsigned long long ad;
                asm("mov.b64 %0, {%1, %1};"
                    : "=l"(ad) : "r"(__float_as_uint(av[i])));
#pragma unroll
                for (int jj = 0; jj < 4; jj++) {
                    asm("fma.rn.f32x2 %0, %1, %2, %0;"
                        : "+l"(acc[i][jj]) : "l"(ad), "l"(bv[jj]));
                }
            }
        }
    }

    // epilogue: + bias + 1e-6, write scratch
    float bb[8];
    *(float4*)(bb)     = *(const float4*)(bias + bn0 + tn*8);
    *(float4*)(bb + 4) = *(const float4*)(bias + bn0 + tn*8 + 4);
#pragma unroll
    for (int i = 0; i < 8; i++) {
        float res[8];
#pragma unroll
        for (int jj = 0; jj < 4; jj++) {
            unsigned lo, hi;
            asm("mov.b64 {%0, %1}, %2;" : "=r"(lo), "=r"(hi) : "l"(acc[i][jj]));
            res[2*jj]   = __uint_as_float(lo) + bb[2*jj]   + 1e-6f;
            res[2*jj+1] = __uint_as_float(hi) + bb[2*jj+1] + 1e-6f;
        }
        float* o = g_w + (size_t)(bm0 + tm*8 + i) * NOUT + bn0 + tn*8;
        *(float4*)o       = make_float4(res[0], res[1], res[2], res[3]);
        *(float4*)(o + 4) = make_float4(res[4], res[5], res[6], res[7]);
    }
}

// ---------------------------------------------------------------------------
// Householder QR (LAPACK convention) — one warp per 64x16 matrix.
// FULLY register-resident: lane l owns rows l and l+32 of A (a0/a1) and of
// Q (q0/q1). No shared memory. All loops over the reflector index j are
// fully unrolled so every register index is static and no predicated-off
// work is issued. Cross-lane traffic = warp reductions + 1 broadcast per j.
// ---------------------------------------------------------------------------
__device__ __forceinline__ float warpsum(float v) {
    v += __shfl_xor_sync(0xffffffffu, v, 16);
    v += __shfl_xor_sync(0xffffffffu, v, 8);
    v += __shfl_xor_sync(0xffffffffu, v, 4);
    v += __shfl_xor_sync(0xffffffffu, v, 2);
    v += __shfl_xor_sync(0xffffffffu, v, 1);
    return v;
}

#define QR_WARPS 4

__global__ void __launch_bounds__(32 * QR_WARPS)
qr_kernel(float* __restrict__ out)
{
    const int warp = threadIdx.x >> 5;
    const int lane = threadIdx.x & 31;
    const size_t b = (size_t)blockIdx.x * QR_WARPS + warp;

    // load matrix: lane owns rows `lane` and `lane+32`
    const float* src = g_w + b * NOUT;
    float a0[QCOLS], a1[QCOLS];
#pragma unroll
    for (int c0 = 0; c0 < QCOLS; c0 += 4) {
        float4 v = *(const float4*)(src + lane * QCOLS + c0);
        a0[c0] = v.x; a0[c0+1] = v.y; a0[c0+2] = v.z; a0[c0+3] = v.w;
        float4 u = *(const float4*)(src + (lane + 32) * QCOLS + c0);
        a1[c0] = u.x; a1[c0+1] = u.y; a1[c0+2] = u.z; a1[c0+3] = u.w;
    }

    float taus[QCOLS];

    // ---- factorization: 16 Householder reflectors (fully unrolled) ----
#pragma unroll
    for (int j = 0; j < QCOLS; j++) {
        float c0v = (lane >= j) ? a0[j] : 0.f;   // column j, rows 0..31
        float c1v = a1[j];                        // column j, rows 32..63
        float p   = warpsum(c0v * c0v + c1v * c1v);   // ||x||^2 incl. x0
        float x0  = __shfl_sync(0xffffffffu, a0[j], j);

        float beta = -copysignf(sqrtf(p), x0);   // LAPACK slarfg
        float tau  = (beta - x0) / beta;
        float sc   = 1.0f / (x0 - beta);

        float v0 = (lane == j) ? 1.0f : c0v * sc;  // lane<j: c0v=0 -> v0=0
        float v1 = c1v * sc;
        a0[j] = v0;                                 // keep v in place
        a1[j] = v1;
        taus[j] = tau;

        // trailing update: batch the independent dots for SHFL ILP
        float pd[QCOLS];
#pragma unroll
        for (int r = j + 1; r < QCOLS; r++)
            pd[r] = v0 * a0[r] + v1 * a1[r];
#pragma unroll
        for (int r = j + 1; r < QCOLS; r++)
            pd[r] = warpsum(pd[r]);
#pragma unroll
        for (int r = j + 1; r < QCOLS; r++) {
            float td = tau * pd[r];
            a0[r] -= td * v0;
            a1[r] -= td * v1;
        }
    }

    // ---- Q = H_0 ... H_15 * I(64x16), backward accumulation (org2r) ----
    float q0[QCOLS], q1[QCOLS];
#pragma unroll
    for (int c = 0; c < QCOLS; c++) {
        q0[c] = (lane == c) ? 1.0f : 0.0f;
        q1[c] = 0.0f;
    }
#pragma unroll
    for (int j = QCOLS - 1; j >= 0; j--) {
        float tau = taus[j];
        float v0  = a0[j];   // 0 for lane<j, 1 at lane==j (stored above)
        float v1  = a1[j];
        float pd[QCOLS];
#pragma unroll
        for (int r = j; r < QCOLS; r++)
            pd[r] = v0 * q0[r] + v1 * q1[r];
#pragma unroll
        for (int r = j; r < QCOLS; r++)
            pd[r] = warpsum(pd[r]);
#pragma unroll
        for (int r = j; r < QCOLS; r++) {
            float td = tau * pd[r];
            q0[r] -= td * v0;
            q1[r] -= td * v1;
        }
    }

    // write Q
    float* dst = out + b * NOUT + lane * QCOLS;
#pragma unroll
    for (int c0 = 0; c0 < QCOLS; c0 += 4) {
        *(float4*)(dst + c0)       = make_float4(q0[c0], q0[c0+1], q0[c0+2], q0[c0+3]);
        *(float4*)(dst + 512 + c0) = make_float4(q1[c0], q1[c0+1], q1[c0+2], q1[c0+3]);
    }
}

// ---------------------------------------------------------------------------
extern "C" void kernel_launch(void* const* d_in, const int* in_sizes, int n_in,
                              void* d_out, int out_size)
{
    const float* z    = (const float*)d_in[0];   // [65536,128]
    const float* W    = (const float*)d_in[1];   // [1024,128]
    const float* bias = (const float*)d_in[2];   // [1024]
    float* out = (float*)d_out;                  // [65536,64,16] fp32

    dim3 ggrid(NOUT / BN, B_TOT / BM);           // (8, 512)
    gemm_kernel<<<ggrid, 256>>>(z, W, bias);
    qr_kernel<<<B_TOT / QR_WARPS, 32 * QR_WARPS>>>(out);
}